// round 1
// baseline (speedup 1.0000x reference)
#include <cuda_runtime.h>
#include <cstdint>

#define IN_FEATURES  8192
#define OUT_FEATURES 8192
#define THRESHOLD    50.0f
#define NTHREADS     256

__global__ __launch_bounds__(NTHREADS)
void snn_fused_kernel(const float* __restrict__ x,
                      const float* __restrict__ syn,
                      const float* __restrict__ mp,
                      const float* __restrict__ thr,
                      const float* __restrict__ elig,
                      float* __restrict__ out) {
    __shared__ float xs[IN_FEATURES];          // 32 KB: spike input, reused twice
    __shared__ float red[NTHREADS / 32];
    __shared__ float spike_sh;

    const int o = blockIdx.x;
    const int t = threadIdx.x;
    const int NV = IN_FEATURES / 4;            // 2048 float4 per row

    // Phase 0: stage x into shared (vectorized)
    const float4* x4  = reinterpret_cast<const float4*>(x);
    float4*       xs4 = reinterpret_cast<float4*>(xs);
    #pragma unroll 4
    for (int i = t; i < NV; i += NTHREADS) xs4[i] = x4[i];
    __syncthreads();

    // Phase 1: current = sum_i x[i] * (syn[o,i] > 50)
    const float4* s4 = reinterpret_cast<const float4*>(syn + (size_t)o * IN_FEATURES);
    float acc = 0.0f;
    #pragma unroll 4
    for (int i = t; i < NV; i += NTHREADS) {
        float4 s  = s4[i];
        float4 xv = xs4[i];
        acc += (s.x > THRESHOLD ? xv.x : 0.0f)
             + (s.y > THRESHOLD ? xv.y : 0.0f)
             + (s.z > THRESHOLD ? xv.z : 0.0f)
             + (s.w > THRESHOLD ? xv.w : 0.0f);
    }
    // warp reduce
    #pragma unroll
    for (int off = 16; off > 0; off >>= 1)
        acc += __shfl_down_sync(0xffffffffu, acc, off);
    if ((t & 31) == 0) red[t >> 5] = acc;
    __syncthreads();

    if (t == 0) {
        float cur = 0.0f;
        #pragma unroll
        for (int w = 0; w < NTHREADS / 32; w++) cur += red[w];
        float v  = mp[o] * 0.6f + cur;
        float sp = (v >= thr[o]) ? 1.0f : 0.0f;
        out[o] = sp;                                   // spikes
        out[OUT_FEATURES + o] = v * (1.0f - sp) * 0.3f; // v_new
        spike_sh = sp;
    }
    __syncthreads();

    // Phase 2: trace_new = clip(elig*0.7 + spike*x, 0, 3)
    const float sp = spike_sh;
    const float4* e4 = reinterpret_cast<const float4*>(elig + (size_t)o * IN_FEATURES);
    float4* o4 = reinterpret_cast<float4*>(out + 2 * (size_t)OUT_FEATURES
                                               + (size_t)o * IN_FEATURES);
    #pragma unroll 4
    for (int i = t; i < NV; i += NTHREADS) {
        float4 e  = e4[i];
        float4 xv = xs4[i];
        float4 r;
        r.x = fminf(fmaxf(fmaf(e.x, 0.7f, sp * xv.x), 0.0f), 3.0f);
        r.y = fminf(fmaxf(fmaf(e.y, 0.7f, sp * xv.y), 0.0f), 3.0f);
        r.z = fminf(fmaxf(fmaf(e.z, 0.7f, sp * xv.z), 0.0f), 3.0f);
        r.w = fminf(fmaxf(fmaf(e.w, 0.7f, sp * xv.w), 0.0f), 3.0f);
        o4[i] = r;
    }
}

extern "C" void kernel_launch(void* const* d_in, const int* in_sizes, int n_in,
                              void* d_out, int out_size) {
    const float* x    = (const float*)d_in[0];  // spike_input [1, 8192]
    const float* syn  = (const float*)d_in[1];  // synapse_states [8192, 8192]
    const float* mp   = (const float*)d_in[2];  // membrane_potential [8192]
    const float* thr  = (const float*)d_in[3];  // adaptive_threshold [8192]
    const float* elig = (const float*)d_in[4];  // eligibility_trace [8192, 8192]
    float* out = (float*)d_out;                 // [spikes | v_new | trace_new]

    snn_fused_kernel<<<OUT_FEATURES, NTHREADS>>>(x, syn, mp, thr, elig, out);
}

// round 2
// speedup vs baseline: 1.1838x; 1.1838x over previous
#include <cuda_runtime.h>
#include <cstdint>

#define IN_F   8192
#define OUT_F  8192
#define THR    50.0f
#define NT     256
#define WARPS  (NT / 32)          // 8 warps per block, one row per warp
#define NV     (IN_F / 4)         // 2048 float4 per row
#define LPW    (NV / 32)          // 64 float4 per lane per row
#define BATCH  8                  // outstanding LDG.128 per lane

__global__ __launch_bounds__(NT)
void snn_warp_kernel(const float* __restrict__ x,
                     const float* __restrict__ syn,
                     const float* __restrict__ mp,
                     const float* __restrict__ thr,
                     const float* __restrict__ elig,
                     float* __restrict__ out) {
    __shared__ float4 xs4[NV];    // 32 KB: spike input, reused by both phases

    const int t = threadIdx.x;
    const int w = t >> 5;
    const int l = t & 31;

    // ── Stage x into shared (once per block) ──
    const float4* x4 = reinterpret_cast<const float4*>(x);
    #pragma unroll
    for (int i = 0; i < NV / NT; i++)
        xs4[t + i * NT] = x4[t + i * NT];
    __syncthreads();              // only barrier in the kernel

    const int o = blockIdx.x * WARPS + w;

    // ── Phase 1: masked row-sum (warp-local, batched loads) ──
    const float4* s4 = reinterpret_cast<const float4*>(syn + (size_t)o * IN_F);
    float acc = 0.0f;
    #pragma unroll
    for (int c = 0; c < LPW; c += BATCH) {
        float4 s[BATCH];
        #pragma unroll
        for (int j = 0; j < BATCH; j++)
            s[j] = __ldcs(&s4[l + (c + j) * 32]);   // front-batched, streaming
        #pragma unroll
        for (int j = 0; j < BATCH; j++) {
            float4 xv = xs4[l + (c + j) * 32];
            acc += (s[j].x > THR ? xv.x : 0.0f)
                 + (s[j].y > THR ? xv.y : 0.0f)
                 + (s[j].z > THR ? xv.z : 0.0f)
                 + (s[j].w > THR ? xv.w : 0.0f);
        }
    }
    // warp-local reduce — no block barrier
    #pragma unroll
    for (int off = 16; off > 0; off >>= 1)
        acc += __shfl_down_sync(0xffffffffu, acc, off);

    float sp = 0.0f;
    if (l == 0) {
        float v = mp[o] * 0.6f + acc;
        sp = (v >= thr[o]) ? 1.0f : 0.0f;
        out[o] = sp;                                    // spikes
        out[OUT_F + o] = v * (1.0f - sp) * 0.3f;        // v_new
    }
    sp = __shfl_sync(0xffffffffu, sp, 0);

    // ── Phase 2: trace_new = clip(elig*0.7 + sp*x, 0, 3) ──
    const float4* e4 = reinterpret_cast<const float4*>(elig + (size_t)o * IN_F);
    float4* o4 = reinterpret_cast<float4*>(out + 2 * (size_t)OUT_F
                                               + (size_t)o * IN_F);
    #pragma unroll
    for (int c = 0; c < LPW; c += BATCH) {
        float4 e[BATCH];
        #pragma unroll
        for (int j = 0; j < BATCH; j++)
            e[j] = __ldcs(&e4[l + (c + j) * 32]);       // front-batched, streaming
        #pragma unroll
        for (int j = 0; j < BATCH; j++) {
            float4 xv = xs4[l + (c + j) * 32];
            float4 r;
            r.x = fminf(fmaxf(fmaf(e[j].x, 0.7f, sp * xv.x), 0.0f), 3.0f);
            r.y = fminf(fmaxf(fmaf(e[j].y, 0.7f, sp * xv.y), 0.0f), 3.0f);
            r.z = fminf(fmaxf(fmaf(e[j].z, 0.7f, sp * xv.z), 0.0f), 3.0f);
            r.w = fminf(fmaxf(fmaf(e[j].w, 0.7f, sp * xv.w), 0.0f), 3.0f);
            __stcs(&o4[l + (c + j) * 32], r);           // streaming store
        }
    }
}

extern "C" void kernel_launch(void* const* d_in, const int* in_sizes, int n_in,
                              void* d_out, int out_size) {
    const float* x    = (const float*)d_in[0];  // spike_input [1, 8192]
    const float* syn  = (const float*)d_in[1];  // synapse_states [8192, 8192]
    const float* mp   = (const float*)d_in[2];  // membrane_potential [8192]
    const float* thr  = (const float*)d_in[3];  // adaptive_threshold [8192]
    const float* elig = (const float*)d_in[4];  // eligibility_trace [8192, 8192]
    float* out = (float*)d_out;                 // [spikes | v_new | trace_new]

    snn_warp_kernel<<<OUT_F / WARPS, NT>>>(x, syn, mp, thr, elig, out);
}